// round 6
// baseline (speedup 1.0000x reference)
#include <cuda_runtime.h>
#include <cuda_bf16.h>

// Shapes (fixed)
#define B_   32
#define P_   16
#define S_   256
#define D_   256
#define NG_  128
#define N_   4096
#define E_   65536
#define H_   256

#define NBLK 128
#define NTHR 1024

// smem layout (static, <48KB): As/Xs union | Bs | sC/scan union
#define AS_STRIDE 260
#define XS_STRIDE 258
#define BS_STRIDE 260
#define OFF_BS 33280            // As: 32*260*4 = 33280
#define OFF_SC 41600            // Bs: 8*260*4  = 8320
#define SMEM_BYTES 45824        // sC: 32*33*4  = 4224 (>= scan 4096)

// ---------------- scratch ----------------------------------------------------
__device__ __align__(16) float g_node_x[N_ * D_];
__device__ float g_dis[N_];
__device__ int   g_cnt[N_];      // zeroed in P3 each launch (init: .bss zero)
__device__ int   g_cursor[N_];   // zeroed in P4
__device__ int   g_offs[N_ + 1];
__device__ __align__(16) int   g_csr_src[E_];
__device__ __align__(16) float g_csr_w[E_];
__device__ float g_C[N_ * B_];   // zeroed in P7 (for next launch)
__device__ __align__(16) float g_part[NBLK * 4 * B_ * H_];
__device__ float g_tmp[B_ * H_];

// grid barrier state
__device__ unsigned g_barcnt;
__device__ unsigned g_barrel;

__device__ __forceinline__ void gbar(unsigned gen0, unsigned k) {
    __syncthreads();
    if (threadIdx.x == 0) {
        __threadfence();
        unsigned a = atomicAdd(&g_barcnt, 1u);
        if (a == NBLK - 1u) {
            g_barcnt = 0;
            __threadfence();
            atomicAdd(&g_barrel, 1u);
        } else {
            for (long long it = 0; it < 50000000LL; ++it) {   // bounded: never hang
                unsigned cur = *(volatile unsigned*)&g_barrel;
                if (cur - gen0 >= k) break;
                __nanosleep(32);
            }
        }
        __threadfence();
    }
    __syncthreads();
}

// packed fp32x2 helpers
__device__ __forceinline__ unsigned long long ffma2(unsigned long long a,
                                                    unsigned long long b,
                                                    unsigned long long c) {
    unsigned long long d;
    asm("fma.rn.f32x2 %0, %1, %2, %3;" : "=l"(d) : "l"(a), "l"(b), "l"(c));
    return d;
}
__device__ __forceinline__ unsigned long long pk2(float x) {
    unsigned long long r; unsigned u = __float_as_uint(x);
    asm("mov.b64 %0, {%1, %2};" : "=l"(r) : "r"(u), "r"(u));
    return r;
}

__global__ void __launch_bounds__(NTHR)
fused_kernel(const float* __restrict__ dge, const int* __restrict__ gids,
             const int* __restrict__ ei,
             const float* __restrict__ W1, const float* __restrict__ b1,
             const float* __restrict__ W2, const float* __restrict__ b2,
             float* __restrict__ out) {
    const int tid = threadIdx.x;
    const int bid = blockIdx.x;
    const int idx = bid * NTHR + tid;    // 0..131071

    unsigned gen0 = 0;
    if (tid == 0) gen0 = *(volatile unsigned*)&g_barrel;

    __shared__ __align__(16) char smem_raw[SMEM_BYTES];
    float* As   = (float*)smem_raw;                 // [32][260] agg rows (k-major cols)
    float* Xs   = (float*)smem_raw;                 // [32][258] x1 (aliases As, post-GEMM)
    float* Bs   = (float*)(smem_raw + OFF_BS);      // [8][260] W1 tile
    float* sC   = (float*)(smem_raw + OFF_SC);      // [32][33]
    int*   s_scan = (int*)(smem_raw + OFF_SC);      // P2 only

    // ---- P1: degree histogram + node_mean -------------------------------
    if (idx < E_) atomicAdd(&g_cnt[ei[E_ + idx]], 1);
    {   // node_mean: 32 nodes/block
        const int lane = tid & 63, sub = tid >> 6;
        const float inv = 1.0f / (float)P_;
#pragma unroll
        for (int r = 0; r < 2; r++) {
            int n = bid * 32 + r * 16 + sub;
            int b = n >> 7;
            int g = gids[n];
            const float4* base = (const float4*)(dge + ((size_t)(b * P_ * S_ + g)) * D_) + lane;
            float sx = 0, sy = 0, sz = 0, sw = 0;
#pragma unroll
            for (int h = 0; h < 2; h++) {
                float4 v[8];
#pragma unroll
                for (int p = 0; p < 8; p++) v[p] = base[(h * 8 + p) * (S_ * D_ / 4)];
#pragma unroll
                for (int p = 0; p < 8; p++) { sx += v[p].x; sy += v[p].y; sz += v[p].z; sw += v[p].w; }
            }
            float4 o; o.x = sx * inv; o.y = sy * inv; o.z = sz * inv; o.w = sw * inv;
            ((float4*)g_node_x)[n * (D_ / 4) + lane] = o;
        }
    }

    gbar(gen0, 1);

    // ---- P2: scan (block 0) + dis (blocks 1..4) -------------------------
    if (bid == 0) {
        int base = tid * 4;
        int v0 = g_cnt[base], v1 = g_cnt[base + 1], v2 = g_cnt[base + 2], v3 = g_cnt[base + 3];
        int tot = v0 + v1 + v2 + v3;
        s_scan[tid] = tot;
        __syncthreads();
        for (int off = 1; off < NTHR; off <<= 1) {
            int x = (tid >= off) ? s_scan[tid - off] : 0;
            __syncthreads();
            s_scan[tid] += x;
            __syncthreads();
        }
        int excl = s_scan[tid] - tot;
        g_offs[base + 0] = excl;
        g_offs[base + 1] = excl + v0;
        g_offs[base + 2] = excl + v0 + v1;
        g_offs[base + 3] = excl + v0 + v1 + v2;
        if (tid == NTHR - 1) g_offs[N_] = excl + tot;
    } else if (bid <= 4) {
        int i = (bid - 1) * NTHR + tid;
        float dv = rsqrtf((float)(g_cnt[i] + 1));   // +1 self-loop
        g_dis[i] = dv;
        g_C[i * B_ + (i >> 7)] = dv * dv;           // self-loop seed (C zeroed last launch)
    }

    gbar(gen0, 2);

    // ---- P3: scatter edges into CSR + C; zero cnt for next launch -------
    if (idx < N_) g_cnt[idx] = 0;
    if (idx < E_) {
        int u = ei[idx];
        int v = ei[E_ + idx];
        float w = g_dis[u] * g_dis[v];
        int pos = g_offs[v] + atomicAdd(&g_cursor[v], 1);
        g_csr_src[pos] = u;
        g_csr_w[pos]   = w;
        atomicAdd(&g_C[u * B_ + (v >> 7)], w);
    }

    gbar(gen0, 3);

    // ---- P456: aggregate -> smem GEMM(relu) -> pool, all block-local ----
    if (idx < N_) g_cursor[idx] = 0;     // reset for next launch
    // load C slice for pool
    sC[(tid >> 5) * 33 + (tid & 31)] = g_C[bid * 1024 + tid];
    // aggregate 32 nodes into As[m][k] (m=node-local, k=feature)
    {
        const int group = tid >> 8;      // 0..3
        const int d = tid & 255;
#pragma unroll 1
        for (int vv = 0; vv < 8; vv++) {
            int ml = group * 8 + vv;
            int v = bid * 32 + ml;
            int beg = g_offs[v], end = g_offs[v + 1];
            float dv = g_dis[v];
            float acc = dv * dv * g_node_x[v * D_ + d];
            float a0 = 0, a1 = 0, a2 = 0, a3 = 0, a4 = 0, a5 = 0, a6 = 0, a7 = 0;
            int i = beg;
            for (; i + 8 <= end; i += 8) {
                int u0 = g_csr_src[i + 0], u1 = g_csr_src[i + 1];
                int u2 = g_csr_src[i + 2], u3 = g_csr_src[i + 3];
                int u4 = g_csr_src[i + 4], u5 = g_csr_src[i + 5];
                int u6 = g_csr_src[i + 6], u7 = g_csr_src[i + 7];
                float w0 = g_csr_w[i + 0], w1 = g_csr_w[i + 1];
                float w2 = g_csr_w[i + 2], w3 = g_csr_w[i + 3];
                float w4 = g_csr_w[i + 4], w5 = g_csr_w[i + 5];
                float w6 = g_csr_w[i + 6], w7 = g_csr_w[i + 7];
                a0 += w0 * g_node_x[u0 * D_ + d];
                a1 += w1 * g_node_x[u1 * D_ + d];
                a2 += w2 * g_node_x[u2 * D_ + d];
                a3 += w3 * g_node_x[u3 * D_ + d];
                a4 += w4 * g_node_x[u4 * D_ + d];
                a5 += w5 * g_node_x[u5 * D_ + d];
                a6 += w6 * g_node_x[u6 * D_ + d];
                a7 += w7 * g_node_x[u7 * D_ + d];
            }
            for (; i < end; i++) a0 += g_csr_w[i] * g_node_x[g_csr_src[i] * D_ + d];
            acc += ((a0 + a1) + (a2 + a3)) + ((a4 + a5) + (a6 + a7));
            As[ml * AS_STRIDE + d] = acc;
        }
    }
    __syncthreads();

    // GEMM: x1(32x256) = relu(As(32x256) @ W1(256x256) + b1)
    // 256 compute threads: tm=tid&7 -> 4 m rows, tn=tid>>3 -> 8 n cols
    // 512 loader threads (tid>=512) prefetch W1 tiles (8x256) reg->smem
    {
        const int tm = tid & 7, tn = tid >> 3;
        unsigned long long acc[4][4];
#pragma unroll
        for (int mi = 0; mi < 4; mi++)
#pragma unroll
            for (int p = 0; p < 4; p++) acc[mi][p] = 0ull;

        float4 pf;
        const int lp = tid - 512;             // loader index 0..511
        if (tid >= 512)
            pf = *(const float4*)&W1[((lp >> 6)) * 256 + (lp & 63) * 4];   // tile 0
        __syncthreads();
        if (tid >= 512)
            *(float4*)&Bs[(lp >> 6) * BS_STRIDE + (lp & 63) * 4] = pf;
        __syncthreads();

        for (int t = 0; t < 32; t++) {
            if (tid >= 512 && t + 1 < 32)
                pf = *(const float4*)&W1[((t + 1) * 8 + (lp >> 6)) * 256 + (lp & 63) * 4];
            if (tid < 256) {
#pragma unroll
                for (int kk = 0; kk < 8; kk++) {
                    int k = t * 8 + kk;
                    unsigned long long a0 = pk2(As[(tm * 4 + 0) * AS_STRIDE + k]);
                    unsigned long long a1 = pk2(As[(tm * 4 + 1) * AS_STRIDE + k]);
                    unsigned long long a2 = pk2(As[(tm * 4 + 2) * AS_STRIDE + k]);
                    unsigned long long a3 = pk2(As[(tm * 4 + 3) * AS_STRIDE + k]);
                    ulonglong2 bp0 = *(const ulonglong2*)&Bs[kk * BS_STRIDE + tn * 8];
                    ulonglong2 bp1 = *(const ulonglong2*)&Bs[kk * BS_STRIDE + tn * 8 + 4];
                    acc[0][0] = ffma2(a0, bp0.x, acc[0][0]); acc[0][1] = ffma2(a0, bp0.y, acc[0][1]);
                    acc[0][2] = ffma2(a0, bp1.x, acc[0][2]); acc[0][3] = ffma2(a0, bp1.y, acc[0][3]);
                    acc[1][0] = ffma2(a1, bp0.x, acc[1][0]); acc[1][1] = ffma2(a1, bp0.y, acc[1][1]);
                    acc[1][2] = ffma2(a1, bp1.x, acc[1][2]); acc[1][3] = ffma2(a1, bp1.y, acc[1][3]);
                    acc[2][0] = ffma2(a2, bp0.x, acc[2][0]); acc[2][1] = ffma2(a2, bp0.y, acc[2][1]);
                    acc[2][2] = ffma2(a2, bp1.x, acc[2][2]); acc[2][3] = ffma2(a2, bp1.y, acc[2][3]);
                    acc[3][0] = ffma2(a3, bp0.x, acc[3][0]); acc[3][1] = ffma2(a3, bp0.y, acc[3][1]);
                    acc[3][2] = ffma2(a3, bp1.x, acc[3][2]); acc[3][3] = ffma2(a3, bp1.y, acc[3][3]);
                }
            }
            __syncthreads();
            if (tid >= 512 && t + 1 < 32)
                *(float4*)&Bs[(lp >> 6) * BS_STRIDE + (lp & 63) * 4] = pf;
            __syncthreads();
        }

        // epilogue: bias + relu -> Xs (overwrites As; all reads done)
        if (tid < 256) {
            float bb[8];
#pragma unroll
            for (int j = 0; j < 8; j++) bb[j] = b1[tn * 8 + j];
#pragma unroll
            for (int mi = 0; mi < 4; mi++) {
                int m = tm * 4 + mi;
#pragma unroll
                for (int p = 0; p < 4; p++) {
                    float lo = __uint_as_float((unsigned)(acc[mi][p] & 0xffffffffull));
                    float hi = __uint_as_float((unsigned)(acc[mi][p] >> 32));
                    float2 o;
                    o.x = fmaxf(lo + bb[p * 2 + 0], 0.0f);
                    o.y = fmaxf(hi + bb[p * 2 + 1], 0.0f);
                    *(float2*)&Xs[m * XS_STRIDE + tn * 8 + p * 2] = o;
                }
            }
        }
    }
    __syncthreads();

    // pool: part[bid*4+q][b][d] = sum_{u in 8 local rows} C[u][b] * x1[u][d]
    {
        const int q = tid >> 8, d = tid & 255;
        float pacc[32];
#pragma unroll
        for (int b = 0; b < 32; b++) pacc[b] = 0.0f;
        for (int uu = 0; uu < 8; uu++) {
            int ml = q * 8 + uu;
            float x = Xs[ml * XS_STRIDE + d];
#pragma unroll
            for (int b = 0; b < 32; b++) pacc[b] += sC[ml * 33 + b] * x;
        }
        int slot = bid * 4 + q;
#pragma unroll
        for (int b = 0; b < 32; b++) g_part[slot * (B_ * H_) + b * 256 + d] = pacc[b];
    }

    gbar(gen0, 4);

    // ---- P7: reduce 512 slots -> tmp; zero C for next launch ------------
    g_C[idx] = 0.0f;                      // idx covers N_*B_ exactly
    {
        int oid = idx >> 4;               // 0..8191
        int part = idx & 15;
        float s = 0.0f;
        int k0 = part * 32;
#pragma unroll 8
        for (int k = 0; k < 32; k++) s += g_part[(k0 + k) * (B_ * H_) + oid];
        s += __shfl_xor_sync(0xffffffffu, s, 1);
        s += __shfl_xor_sync(0xffffffffu, s, 2);
        s += __shfl_xor_sync(0xffffffffu, s, 4);
        s += __shfl_xor_sync(0xffffffffu, s, 8);
        if (part == 0) g_tmp[oid] = s;
    }

    gbar(gen0, 5);

    // ---- P8: out = tmp @ W2 / NG + b2 (16 threads per output) -----------
    {
        int oid = idx >> 4;
        int part = idx & 15;
        int b = oid >> 8, h = oid & 255;
        const float* tr = g_tmp + b * 256 + part * 16;
        const float* w2 = W2 + (part * 16) * 256 + h;
        float acc = 0.0f;
#pragma unroll 8
        for (int d = 0; d < 16; d++) acc += tr[d] * w2[d * 256];
        acc += __shfl_xor_sync(0xffffffffu, acc, 1);
        acc += __shfl_xor_sync(0xffffffffu, acc, 2);
        acc += __shfl_xor_sync(0xffffffffu, acc, 4);
        acc += __shfl_xor_sync(0xffffffffu, acc, 8);
        if (part == 0) out[oid] = acc * (1.0f / NG_) + b2[h];
    }
}

// ---------------- launch -----------------------------------------------------
extern "C" void kernel_launch(void* const* d_in, const int* in_sizes, int n_in,
                              void* d_out, int out_size) {
    const float* dge  = (const float*)d_in[0];
    const int*   gids = (const int*)  d_in[1];
    const int*   ei   = (const int*)  d_in[2];
    const float* W1   = (const float*)d_in[3];
    const float* b1   = (const float*)d_in[4];
    const float* W2   = (const float*)d_in[5];
    const float* b2   = (const float*)d_in[6];
    float* out = (float*)d_out;

    fused_kernel<<<NBLK, NTHR>>>(dge, gids, ei, W1, b1, W2, b2, out);
}

// round 10
// speedup vs baseline: 1.0254x; 1.0254x over previous
#include <cuda_runtime.h>
#include <cuda_bf16.h>

// Shapes (fixed)
#define B_   32
#define P_   16
#define S_   256
#define D_   256
#define NG_  128
#define N_   4096
#define E_   65536
#define H_   256

// ---------------- scratch ----------------------------------------------------
__device__ __align__(16) float g_node_x[N_ * D_];
__device__ float g_dis[N_];
__device__ int   g_cnt[N_];      // zeroed in graph_build phase C
__device__ int   g_cursor[N_];   // zeroed in k_agp
__device__ int   g_offs[N_ + 1];
__device__ __align__(16) int   g_csr_src[E_];
__device__ __align__(16) float g_csr_w[E_];
__device__ float g_C[N_ * B_];   // zeroed in k_final (for next replay)
__device__ __align__(16) float g_part[512 * B_ * H_];

// grid barrier (used only inside k_graph_build, 128 blocks)
__device__ unsigned g_barcnt;
__device__ unsigned g_barrel;

__device__ __forceinline__ void gbar128(unsigned gen0, unsigned k) {
    __syncthreads();
    if (threadIdx.x == 0) {
        __threadfence();
        unsigned a = atomicAdd(&g_barcnt, 1u);
        if (a == 127u) {
            g_barcnt = 0;
            __threadfence();
            atomicAdd(&g_barrel, 1u);
        } else {
            for (long long it = 0; it < 50000000LL; ++it) {
                unsigned cur = *(volatile unsigned*)&g_barrel;
                if (cur - gen0 >= k) break;
                __nanosleep(32);
            }
        }
        __threadfence();
    }
    __syncthreads();
}

// packed fp32x2 helpers
__device__ __forceinline__ unsigned long long ffma2(unsigned long long a,
                                                    unsigned long long b,
                                                    unsigned long long c) {
    unsigned long long d;
    asm("fma.rn.f32x2 %0, %1, %2, %3;" : "=l"(d) : "l"(a), "l"(b), "l"(c));
    return d;
}
__device__ __forceinline__ unsigned long long pk2(float x) {
    unsigned long long r; unsigned u = __float_as_uint(x);
    asm("mov.b64 %0, {%1, %2};" : "=l"(r) : "r"(u), "r"(u));
    return r;
}

// ===== K1: node_mean — pure DRAM phase, max MLP =============================
// 1024 blocks x 256 thr; thread t -> node n = t>>6, lane = t&63 (16B chunk)
__global__ void __launch_bounds__(256)
k_node_mean(const float* __restrict__ dge, const int* __restrict__ gids) {
    int t = blockIdx.x * 256 + threadIdx.x;
    int n = t >> 6, lane = t & 63;
    int b = n >> 7;
    int g = __ldg(&gids[n]);
    const float4* base = (const float4*)(dge + ((size_t)(b * P_ * S_ + g)) * D_) + lane;
    float4 v[16];
#pragma unroll
    for (int p = 0; p < 16; p++) v[p] = base[p * (S_ * D_ / 4)];   // 16 LDG.128 in flight
    float sx = 0, sy = 0, sz = 0, sw = 0;
#pragma unroll
    for (int p = 0; p < 16; p++) { sx += v[p].x; sy += v[p].y; sz += v[p].z; sw += v[p].w; }
    const float inv = 1.0f / (float)P_;
    float4 o; o.x = sx * inv; o.y = sy * inv; o.z = sz * inv; o.w = sw * inv;
    ((float4*)g_node_x)[n * (D_ / 4) + lane] = o;
}

// ===== K2: graph build — deg, scan, dis, scatter (128 blocks x 512) =========
__global__ void __launch_bounds__(512)
k_graph_build(const int* __restrict__ ei) {
    const int tid = threadIdx.x, bid = blockIdx.x;
    const int idx = bid * 512 + tid;          // 0..65535 == E
    __shared__ int s_scan[512];

    unsigned gen0 = 0;
    if (tid == 0) gen0 = *(volatile unsigned*)&g_barrel;

    // A: degree histogram + zero C (131072 = 2*E)
    atomicAdd(&g_cnt[ei[E_ + idx]], 1);
    g_C[idx] = 0.0f;
    g_C[idx + E_] = 0.0f;

    gbar128(gen0, 1);

    // B: scan (block 0) + dis/Cseed (blocks 1..8)
    if (bid == 0) {
        int base = tid * 8;
        int vals[8]; int tot = 0;
#pragma unroll
        for (int j = 0; j < 8; j++) { vals[j] = g_cnt[base + j]; tot += vals[j]; }
        s_scan[tid] = tot;
        __syncthreads();
        for (int off = 1; off < 512; off <<= 1) {
            int x = (tid >= off) ? s_scan[tid - off] : 0;
            __syncthreads();
            s_scan[tid] += x;
            __syncthreads();
        }
        int excl = s_scan[tid] - tot;
#pragma unroll
        for (int j = 0; j < 8; j++) { g_offs[base + j] = excl; excl += vals[j]; }
        if (tid == 511) g_offs[N_] = excl;
    } else if (bid <= 8) {
        int i = (bid - 1) * 512 + tid;
        float dv = rsqrtf((float)(g_cnt[i] + 1));
        g_dis[i] = dv;
        g_C[i * B_ + (i >> 7)] = dv * dv;     // self-loop seed
    }

    gbar128(gen0, 2);

    // C: scatter into CSR + C; zero cnt for next replay
    if (idx < N_) g_cnt[idx] = 0;
    {
        int u = ei[idx];
        int v = ei[E_ + idx];
        float w = g_dis[u] * g_dis[v];
        int pos = g_offs[v] + atomicAdd(&g_cursor[v], 1);
        g_csr_src[pos] = u;
        g_csr_w[pos]   = w;
        atomicAdd(&g_C[u * B_ + (v >> 7)], w);
    }
}

// ===== K3: aggregate -> GEMM(relu) -> pool (128 blocks x 1024) ==============
#define AS_STRIDE 260
#define XS_STRIDE 258
#define BS_STRIDE 260   // 260*4 = 1040 B, 16B multiple -> float4 rows aligned
__global__ void __launch_bounds__(1024)
k_agp(const float* __restrict__ W1, const float* __restrict__ b1) {
    const int tid = threadIdx.x, bid = blockIdx.x;
    const int idx = bid * 1024 + tid;

    __shared__ __align__(16) float As[32 * AS_STRIDE];   // 33280 B
    __shared__ __align__(16) float Bs[8 * BS_STRIDE];    // 8320 B
    __shared__ __align__(16) float sC[32 * 33];          // 4224 B
    float* Xs = As;                                      // alias post-GEMM

    if (idx < N_) g_cursor[idx] = 0;                     // reset for next replay
    sC[(tid >> 5) * 33 + (tid & 31)] = g_C[bid * 1024 + tid];

    // aggregate 32 nodes into As[m][k]
    {
        const int group = tid >> 8;          // 0..3
        const int d = tid & 255;
#pragma unroll 1
        for (int vv = 0; vv < 8; vv++) {
            int ml = group * 8 + vv;
            int v = bid * 32 + ml;
            int beg = g_offs[v], end = g_offs[v + 1];
            float dv = g_dis[v];
            float acc = dv * dv * g_node_x[v * D_ + d];
            float a0 = 0, a1 = 0, a2 = 0, a3 = 0, a4 = 0, a5 = 0, a6 = 0, a7 = 0;
            int i = beg;
            for (; i + 8 <= end; i += 8) {
                int u0 = g_csr_src[i + 0], u1 = g_csr_src[i + 1];
                int u2 = g_csr_src[i + 2], u3 = g_csr_src[i + 3];
                int u4 = g_csr_src[i + 4], u5 = g_csr_src[i + 5];
                int u6 = g_csr_src[i + 6], u7 = g_csr_src[i + 7];
                float w0 = g_csr_w[i + 0], w1 = g_csr_w[i + 1];
                float w2 = g_csr_w[i + 2], w3 = g_csr_w[i + 3];
                float w4 = g_csr_w[i + 4], w5 = g_csr_w[i + 5];
                float w6 = g_csr_w[i + 6], w7 = g_csr_w[i + 7];
                a0 += w0 * g_node_x[u0 * D_ + d];
                a1 += w1 * g_node_x[u1 * D_ + d];
                a2 += w2 * g_node_x[u2 * D_ + d];
                a3 += w3 * g_node_x[u3 * D_ + d];
                a4 += w4 * g_node_x[u4 * D_ + d];
                a5 += w5 * g_node_x[u5 * D_ + d];
                a6 += w6 * g_node_x[u6 * D_ + d];
                a7 += w7 * g_node_x[u7 * D_ + d];
            }
            for (; i < end; i++) a0 += g_csr_w[i] * g_node_x[g_csr_src[i] * D_ + d];
            acc += ((a0 + a1) + (a2 + a3)) + ((a4 + a5) + (a6 + a7));
            As[ml * AS_STRIDE + d] = acc;
        }
    }
    __syncthreads();

    // GEMM: 1024 compute threads, 4m x 2n each; A warp-uniform broadcast
    {
        const int mg = tid >> 7;             // 0..7 -> rows mg*4..mg*4+3 (warp-uniform)
        const int tn = tid & 127;            // 0..127 -> cols tn*2, tn*2+1
        unsigned long long acc[4];
        acc[0] = acc[1] = acc[2] = acc[3] = 0ull;

        for (int t = 0; t < 32; t++) {
            if (tid < 512) {   // load W1 tile 8x256 (one float4 each)
                int row = tid >> 6, nq = (tid & 63) * 4;
                *(float4*)&Bs[row * BS_STRIDE + nq] = *(const float4*)&W1[(t * 8 + row) * 256 + nq];
            }
            __syncthreads();
#pragma unroll
            for (int kk = 0; kk < 8; kk++) {
                int k = t * 8 + kk;
                unsigned long long bp = *(const unsigned long long*)&Bs[kk * BS_STRIDE + tn * 2];
                unsigned long long a0 = pk2(As[(mg * 4 + 0) * AS_STRIDE + k]);
                unsigned long long a1 = pk2(As[(mg * 4 + 1) * AS_STRIDE + k]);
                unsigned long long a2 = pk2(As[(mg * 4 + 2) * AS_STRIDE + k]);
                unsigned long long a3 = pk2(As[(mg * 4 + 3) * AS_STRIDE + k]);
                acc[0] = ffma2(a0, bp, acc[0]);
                acc[1] = ffma2(a1, bp, acc[1]);
                acc[2] = ffma2(a2, bp, acc[2]);
                acc[3] = ffma2(a3, bp, acc[3]);
            }
            __syncthreads();
        }

        float blo = b1[tn * 2], bhi = b1[tn * 2 + 1];
        __syncthreads();   // all As reads done before overwrite
#pragma unroll
        for (int mi = 0; mi < 4; mi++) {
            float lo = __uint_as_float((unsigned)(acc[mi] & 0xffffffffull));
            float hi = __uint_as_float((unsigned)(acc[mi] >> 32));
            float2 o;
            o.x = fmaxf(lo + blo, 0.0f);
            o.y = fmaxf(hi + bhi, 0.0f);
            *(float2*)&Xs[(mg * 4 + mi) * XS_STRIDE + tn * 2] = o;
        }
    }
    __syncthreads();

    // pool: 4 quarters x 8 rows -> g_part[bid*4+q]
    {
        const int q = tid >> 8, d = tid & 255;
        float pacc[32];
#pragma unroll
        for (int b = 0; b < 32; b++) pacc[b] = 0.0f;
        for (int uu = 0; uu < 8; uu++) {
            int ml = q * 8 + uu;
            float x = Xs[ml * XS_STRIDE + d];
#pragma unroll
            for (int b = 0; b < 32; b++) pacc[b] += sC[ml * 33 + b] * x;
        }
        int slot = bid * 4 + q;
#pragma unroll
        for (int b = 0; b < 32; b++) g_part[slot * (B_ * H_) + b * 256 + d] = pacc[b];
    }
}

// ===== K4: reduce partials + W2 + bias (32 blocks x 256) ====================
__global__ void __launch_bounds__(256)
k_final(const float* __restrict__ W2, const float* __restrict__ b2,
        float* __restrict__ out) {
    const int tid = threadIdx.x, b = blockIdx.x;
    __shared__ float sm[256];

    // zero C for next replay (grid-stride over 131072)
    for (int i = b * 256 + tid; i < N_ * B_; i += 32 * 256) g_C[i] = 0.0f;

    // tmp[b][d] = sum over 512 slots
    {
        float s = 0.0f;
        const float* p = g_part + b * 256 + tid;
#pragma unroll 8
        for (int k = 0; k < 512; k++) s += p[(size_t)k * (B_ * H_)];
        sm[tid] = s;
    }
    __syncthreads();

    // out[b][h] = (sm . W2[:,h]) / NG + b2[h]
    {
        float acc = 0.0f;
        const float* w2 = W2 + tid;
#pragma unroll 8
        for (int d = 0; d < 256; d++) acc += sm[d] * w2[d * 256];
        out[b * 256 + tid] = acc * (1.0f / NG_) + b2[tid];
    }
}

// ---------------- launch -----------------------------------------------------
extern "C" void kernel_launch(void* const* d_in, const int* in_sizes, int n_in,
                              void* d_out, int out_size) {
    const float* dge  = (const float*)d_in[0];
    const int*   gids = (const int*)  d_in[1];
    const int*   ei   = (const int*)  d_in[2];
    const float* W1   = (const float*)d_in[3];
    const float* b1   = (const float*)d_in[4];
    const float* W2   = (const float*)d_in[5];
    const float* b2   = (const float*)d_in[6];
    float* out = (float*)d_out;

    k_node_mean<<<1024, 256>>>(dge, gids);
    k_graph_build<<<128, 512>>>(ei);
    k_agp<<<128, 1024>>>(W1, b1);
    k_final<<<32, 256>>>(W2, b2, out);
}

// round 12
// speedup vs baseline: 1.3996x; 1.3650x over previous
#include <cuda_runtime.h>
#include <cuda_bf16.h>

// Shapes (fixed)
#define B_   32
#define P_   16
#define S_   256
#define D_   256
#define NG_  128
#define N_   4096
#define E_   65536
#define H_   256

// ---------------- scratch ----------------------------------------------------
__device__ __align__(16) float g_node_x[N_ * D_];
__device__ float g_dis[N_];
__device__ int   g_cnt[N_];      // zeroed in k_graph_build phase C
__device__ int   g_cursor[N_];   // zeroed in k_agp
__device__ int   g_offs[N_ + 1];
__device__ __align__(16) int   g_csr_src[E_];
__device__ __align__(16) float g_csr_w[E_];
__device__ float g_C[N_ * B_];   // zeroed in k_reduce (for next replay)
__device__ __align__(16) float g_part[128 * B_ * H_];   // 128 slots x 8192 = 4 MB
__device__ float g_tmp[B_ * H_];

// grid barrier (used only inside k_graph_build, 128 blocks)
__device__ unsigned g_barcnt;
__device__ unsigned g_barrel;

__device__ __forceinline__ void gbar128(unsigned gen0, unsigned k) {
    __syncthreads();
    if (threadIdx.x == 0) {
        __threadfence();
        unsigned a = atomicAdd(&g_barcnt, 1u);
        if (a == 127u) {
            g_barcnt = 0;
            __threadfence();
            atomicAdd(&g_barrel, 1u);
        } else {
            for (long long it = 0; it < 50000000LL; ++it) {
                unsigned cur = *(volatile unsigned*)&g_barrel;
                if (cur - gen0 >= k) break;
                __nanosleep(32);
            }
        }
        __threadfence();
    }
    __syncthreads();
}

// packed fp32x2 helpers
__device__ __forceinline__ unsigned long long ffma2(unsigned long long a,
                                                    unsigned long long b,
                                                    unsigned long long c) {
    unsigned long long d;
    asm("fma.rn.f32x2 %0, %1, %2, %3;" : "=l"(d) : "l"(a), "l"(b), "l"(c));
    return d;
}
__device__ __forceinline__ unsigned long long pk2(float x) {
    unsigned long long r; unsigned u = __float_as_uint(x);
    asm("mov.b64 %0, {%1, %2};" : "=l"(r) : "r"(u), "r"(u));
    return r;
}

// ===== K1: node_mean (1024 blocks x 256) ====================================
__global__ void __launch_bounds__(256)
k_node_mean(const float* __restrict__ dge, const int* __restrict__ gids) {
    int t = blockIdx.x * 256 + threadIdx.x;
    int n = t >> 6, lane = t & 63;
    int b = n >> 7;
    int g = __ldg(&gids[n]);
    const float4* base = (const float4*)(dge + ((size_t)(b * P_ * S_ + g)) * D_) + lane;
    float4 v[16];
#pragma unroll
    for (int p = 0; p < 16; p++) v[p] = base[p * (S_ * D_ / 4)];
    float sx = 0, sy = 0, sz = 0, sw = 0;
#pragma unroll
    for (int p = 0; p < 16; p++) { sx += v[p].x; sy += v[p].y; sz += v[p].z; sw += v[p].w; }
    const float inv = 1.0f / (float)P_;
    float4 o; o.x = sx * inv; o.y = sy * inv; o.z = sz * inv; o.w = sw * inv;
    ((float4*)g_node_x)[n * (D_ / 4) + lane] = o;
}

// ===== K2: graph build (128 blocks x 512) ===================================
__global__ void __launch_bounds__(512)
k_graph_build(const int* __restrict__ ei) {
    const int tid = threadIdx.x, bid = blockIdx.x;
    const int idx = bid * 512 + tid;          // 0..65535 == E
    __shared__ int s_scan[512];

    unsigned gen0 = 0;
    if (tid == 0) gen0 = *(volatile unsigned*)&g_barrel;

    // A: degree histogram (C already zeroed by previous k_reduce / .bss)
    atomicAdd(&g_cnt[ei[E_ + idx]], 1);

    gbar128(gen0, 1);

    // B: scan (block 0) + dis/Cseed (blocks 1..8)
    if (bid == 0) {
        int base = tid * 8;
        int vals[8]; int tot = 0;
#pragma unroll
        for (int j = 0; j < 8; j++) { vals[j] = g_cnt[base + j]; tot += vals[j]; }
        s_scan[tid] = tot;
        __syncthreads();
        for (int off = 1; off < 512; off <<= 1) {
            int x = (tid >= off) ? s_scan[tid - off] : 0;
            __syncthreads();
            s_scan[tid] += x;
            __syncthreads();
        }
        int excl = s_scan[tid] - tot;
#pragma unroll
        for (int j = 0; j < 8; j++) { g_offs[base + j] = excl; excl += vals[j]; }
        if (tid == 511) g_offs[N_] = excl;
    } else if (bid <= 8) {
        int i = (bid - 1) * 512 + tid;
        float dv = rsqrtf((float)(g_cnt[i] + 1));
        g_dis[i] = dv;
        g_C[i * B_ + (i >> 7)] = dv * dv;     // self-loop seed (overwrite)
    }

    gbar128(gen0, 2);

    // C: scatter into CSR + C; zero cnt for next replay
    if (idx < N_) g_cnt[idx] = 0;
    {
        int u = ei[idx];
        int v = ei[E_ + idx];
        float w = g_dis[u] * g_dis[v];
        int pos = g_offs[v] + atomicAdd(&g_cursor[v], 1);
        g_csr_src[pos] = u;
        g_csr_w[pos]   = w;
        atomicAdd(&g_C[u * B_ + (v >> 7)], w);
    }
}

// ===== K3: aggregate -> GEMM(relu) -> pool (128 blocks x 1024) ==============
__global__ void __launch_bounds__(1024)
k_agp(const float* __restrict__ W1, const float* __restrict__ b1) {
    const int tid = threadIdx.x, bid = blockIdx.x;
    const int idx = bid * 1024 + tid;

    __shared__ __align__(16) float As[32 * 256];     // 32768 B (stride 256: reads are
    __shared__ __align__(16) float Bs[8 * 256];      //  8192 B  broadcast or stride-1)
    __shared__ __align__(16) float sC[32 * 33];      //  4224 B
    float* Xs = As;                                  // alias post-GEMM

    if (idx < N_) g_cursor[idx] = 0;                 // reset for next replay
    sC[(tid >> 5) * 33 + (tid & 31)] = g_C[bid * 1024 + tid];

    // aggregate 32 nodes into As[m][k]
    {
        const int group = tid >> 8;          // 0..3
        const int d = tid & 255;
#pragma unroll 1
        for (int vv = 0; vv < 8; vv++) {
            int ml = group * 8 + vv;
            int v = bid * 32 + ml;
            int beg = g_offs[v], end = g_offs[v + 1];
            float dv = g_dis[v];
            float acc = dv * dv * g_node_x[v * D_ + d];
            float a0 = 0, a1 = 0, a2 = 0, a3 = 0, a4 = 0, a5 = 0, a6 = 0, a7 = 0;
            int i = beg;
            for (; i + 8 <= end; i += 8) {
                int u0 = g_csr_src[i + 0], u1 = g_csr_src[i + 1];
                int u2 = g_csr_src[i + 2], u3 = g_csr_src[i + 3];
                int u4 = g_csr_src[i + 4], u5 = g_csr_src[i + 5];
                int u6 = g_csr_src[i + 6], u7 = g_csr_src[i + 7];
                float w0 = g_csr_w[i + 0], w1 = g_csr_w[i + 1];
                float w2 = g_csr_w[i + 2], w3 = g_csr_w[i + 3];
                float w4 = g_csr_w[i + 4], w5 = g_csr_w[i + 5];
                float w6 = g_csr_w[i + 6], w7 = g_csr_w[i + 7];
                a0 += w0 * g_node_x[u0 * D_ + d];
                a1 += w1 * g_node_x[u1 * D_ + d];
                a2 += w2 * g_node_x[u2 * D_ + d];
                a3 += w3 * g_node_x[u3 * D_ + d];
                a4 += w4 * g_node_x[u4 * D_ + d];
                a5 += w5 * g_node_x[u5 * D_ + d];
                a6 += w6 * g_node_x[u6 * D_ + d];
                a7 += w7 * g_node_x[u7 * D_ + d];
            }
            for (; i < end; i++) a0 += g_csr_w[i] * g_node_x[g_csr_src[i] * D_ + d];
            acc += ((a0 + a1) + (a2 + a3)) + ((a4 + a5) + (a6 + a7));
            As[ml * 256 + d] = acc;
        }
    }
    __syncthreads();

    // GEMM: 256 compute threads (4m x 8n each), 512 loader threads (tid>=512)
    // n cols: tn*4..tn*4+3 and 128+tn*4..+3 (16B-strided lanes -> conflict-free LDS.128)
    {
        const int mg = tid >> 5;             // 0..7 (m rows mg*4..mg*4+3), warp-uniform
        const int tn = tid & 31;             // 0..31
        unsigned long long acc[4][4];        // [mi][chunk*2+pair]
#pragma unroll
        for (int mi = 0; mi < 4; mi++)
#pragma unroll
            for (int p = 0; p < 4; p++) acc[mi][p] = 0ull;

        const int lp = tid - 512;
        for (int t = 0; t < 32; t++) {
            if (tid >= 512) {   // load W1 tile 8x256, one float4 each
                int row = lp >> 6, nq = (lp & 63) * 4;
                *(float4*)&Bs[row * 256 + nq] = *(const float4*)&W1[(t * 8 + row) * 256 + nq];
            }
            __syncthreads();
            if (tid < 256) {
#pragma unroll
                for (int kk = 0; kk < 8; kk++) {
                    int k = t * 8 + kk;
                    ulonglong2 bp0 = *(const ulonglong2*)&Bs[kk * 256 + tn * 4];
                    ulonglong2 bp1 = *(const ulonglong2*)&Bs[kk * 256 + 128 + tn * 4];
                    unsigned long long a0 = pk2(As[(mg * 4 + 0) * 256 + k]);
                    unsigned long long a1 = pk2(As[(mg * 4 + 1) * 256 + k]);
                    unsigned long long a2 = pk2(As[(mg * 4 + 2) * 256 + k]);
                    unsigned long long a3 = pk2(As[(mg * 4 + 3) * 256 + k]);
                    acc[0][0] = ffma2(a0, bp0.x, acc[0][0]); acc[0][1] = ffma2(a0, bp0.y, acc[0][1]);
                    acc[0][2] = ffma2(a0, bp1.x, acc[0][2]); acc[0][3] = ffma2(a0, bp1.y, acc[0][3]);
                    acc[1][0] = ffma2(a1, bp0.x, acc[1][0]); acc[1][1] = ffma2(a1, bp0.y, acc[1][1]);
                    acc[1][2] = ffma2(a1, bp1.x, acc[1][2]); acc[1][3] = ffma2(a1, bp1.y, acc[1][3]);
                    acc[2][0] = ffma2(a2, bp0.x, acc[2][0]); acc[2][1] = ffma2(a2, bp0.y, acc[2][1]);
                    acc[2][2] = ffma2(a2, bp1.x, acc[2][2]); acc[2][3] = ffma2(a2, bp1.y, acc[2][3]);
                    acc[3][0] = ffma2(a3, bp0.x, acc[3][0]); acc[3][1] = ffma2(a3, bp0.y, acc[3][1]);
                    acc[3][2] = ffma2(a3, bp1.x, acc[3][2]); acc[3][3] = ffma2(a3, bp1.y, acc[3][3]);
                }
            }
            __syncthreads();
        }

        if (tid < 256) {
            float bb[2][4];
#pragma unroll
            for (int j = 0; j < 4; j++) { bb[0][j] = b1[tn * 4 + j]; bb[1][j] = b1[128 + tn * 4 + j]; }
            __syncthreads();   // As reads complete everywhere before overwrite
#pragma unroll
            for (int mi = 0; mi < 4; mi++) {
                int m = mg * 4 + mi;
#pragma unroll
                for (int c = 0; c < 2; c++) {
#pragma unroll
                    for (int p = 0; p < 2; p++) {
                        unsigned long long a = acc[mi][c * 2 + p];
                        float lo = __uint_as_float((unsigned)(a & 0xffffffffull));
                        float hi = __uint_as_float((unsigned)(a >> 32));
                        float2 o;
                        o.x = fmaxf(lo + bb[c][p * 2 + 0], 0.0f);
                        o.y = fmaxf(hi + bb[c][p * 2 + 1], 0.0f);
                        *(float2*)&Xs[m * 256 + c * 128 + tn * 4 + p * 2] = o;
                    }
                }
            }
        } else {
            __syncthreads();   // matching barrier for non-compute threads
        }
    }
    __syncthreads();

    // pool (b-split): thread (q,d) -> 8 batch values over all 32 rows; ONE slot/block
    {
        const int q = tid >> 8, d = tid & 255;
        float pacc[8];
#pragma unroll
        for (int bi = 0; bi < 8; bi++) pacc[bi] = 0.0f;
        for (int ml = 0; ml < 32; ml++) {
            float x = Xs[ml * 256 + d];
#pragma unroll
            for (int bi = 0; bi < 8; bi++) pacc[bi] += sC[ml * 33 + q * 8 + bi] * x;
        }
#pragma unroll
        for (int bi = 0; bi < 8; bi++)
            g_part[bid * (B_ * H_) + (q * 8 + bi) * 256 + d] = pacc[bi];
    }
}

// ===== K4a: reduce 128 slots -> tmp (128 blocks x 256); zero C ==============
__global__ void __launch_bounds__(256)
k_reduce() {
    const int idx = blockIdx.x * 256 + threadIdx.x;   // 0..32767
#pragma unroll
    for (int j = 0; j < 4; j++) g_C[j * 32768 + idx] = 0.0f;   // next replay

    const int o_local = threadIdx.x >> 2;     // 0..63
    const int part = threadIdx.x & 3;         // 0..3
    const int oid = blockIdx.x * 64 + o_local;
    const float* p = g_part + (size_t)(part * 32) * (B_ * H_) + oid;
    float s = 0.0f;
#pragma unroll
    for (int k = 0; k < 32; k++) s += p[(size_t)k * (B_ * H_)];
    s += __shfl_xor_sync(0xffffffffu, s, 1);
    s += __shfl_xor_sync(0xffffffffu, s, 2);
    if (part == 0) g_tmp[oid] = s;
}

// ===== K4b: out = tmp @ W2 / NG + b2 (32 blocks x 256) ======================
__global__ void __launch_bounds__(256)
k_final2(const float* __restrict__ W2, const float* __restrict__ b2,
         float* __restrict__ out) {
    const int tid = threadIdx.x, b = blockIdx.x;
    __shared__ float sm[256];
    sm[tid] = g_tmp[b * 256 + tid];
    __syncthreads();
    float acc = 0.0f;
    const float* w2 = W2 + tid;
#pragma unroll 16
    for (int d = 0; d < 256; d++) acc += sm[d] * w2[d * 256];
    out[b * 256 + tid] = acc * (1.0f / NG_) + b2[tid];
}

// ---------------- launch -----------------------------------------------------
extern "C" void kernel_launch(void* const* d_in, const int* in_sizes, int n_in,
                              void* d_out, int out_size) {
    const float* dge  = (const float*)d_in[0];
    const int*   gids = (const int*)  d_in[1];
    const int*   ei   = (const int*)  d_in[2];
    const float* W1   = (const float*)d_in[3];
    const float* b1   = (const float*)d_in[4];
    const float* W2   = (const float*)d_in[5];
    const float* b2   = (const float*)d_in[6];
    float* out = (float*)d_out;

    k_node_mean<<<1024, 256>>>(dge, gids);
    k_graph_build<<<128, 512>>>(ei);
    k_agp<<<128, 1024>>>(W1, b1);
    k_reduce<<<128, 256>>>();
    k_final2<<<32, 256>>>(W2, b2, out);
}

// round 15
// speedup vs baseline: 1.4965x; 1.0693x over previous
#include <cuda_runtime.h>
#include <cuda_bf16.h>

// Shapes (fixed)
#define B_   32
#define P_   16
#define S_   256
#define D_   256
#define NG_  128
#define N_   4096
#define E_   65536
#define H_   256

// ---------------- scratch ----------------------------------------------------
__device__ __align__(16) float g_node_x[N_ * D_];
__device__ float g_dis[N_];
__device__ int   g_cnt[N_];      // zeroed in k_graph_build phase C
__device__ int   g_cursor[N_];   // zeroed in k_agp
__device__ int   g_offs[N_ + 1];
__device__ __align__(16) int   g_csr_src[E_];
__device__ __align__(16) float g_csr_w[E_];
__device__ float g_C[N_ * B_];   // zeroed in k_final2 (for next replay)
__device__ float g_tmp[B_ * H_]; // pool accumulator; zeroed in k_graph_build

// grid barrier (used only inside k_graph_build, 128 blocks)
__device__ unsigned g_barcnt;
__device__ unsigned g_barrel;

__device__ __forceinline__ void gbar128(unsigned gen0, unsigned k) {
    __syncthreads();
    if (threadIdx.x == 0) {
        __threadfence();
        unsigned a = atomicAdd(&g_barcnt, 1u);
        if (a == 127u) {
            g_barcnt = 0;
            __threadfence();
            atomicAdd(&g_barrel, 1u);
        } else {
            for (long long it = 0; it < 50000000LL; ++it) {
                unsigned cur = *(volatile unsigned*)&g_barrel;
                if (cur - gen0 >= k) break;
                __nanosleep(32);
            }
        }
        __threadfence();
    }
    __syncthreads();
}

// packed fp32x2 helpers
__device__ __forceinline__ unsigned long long ffma2(unsigned long long a,
                                                    unsigned long long b,
                                                    unsigned long long c) {
    unsigned long long d;
    asm("fma.rn.f32x2 %0, %1, %2, %3;" : "=l"(d) : "l"(a), "l"(b), "l"(c));
    return d;
}
__device__ __forceinline__ unsigned long long pk2(float x) {
    unsigned long long r; unsigned u = __float_as_uint(x);
    asm("mov.b64 %0, {%1, %2};" : "=l"(r) : "r"(u), "r"(u));
    return r;
}

// ===== K1: node_mean (1024 blocks x 256) ====================================
__global__ void __launch_bounds__(256)
k_node_mean(const float* __restrict__ dge, const int* __restrict__ gids) {
    int t = blockIdx.x * 256 + threadIdx.x;
    int n = t >> 6, lane = t & 63;
    int b = n >> 7;
    int g = __ldg(&gids[n]);
    const float4* base = (const float4*)(dge + ((size_t)(b * P_ * S_ + g)) * D_) + lane;
    float4 v[16];
#pragma unroll
    for (int p = 0; p < 16; p++) v[p] = base[p * (S_ * D_ / 4)];
    float sx = 0, sy = 0, sz = 0, sw = 0;
#pragma unroll
    for (int p = 0; p < 16; p++) { sx += v[p].x; sy += v[p].y; sz += v[p].z; sw += v[p].w; }
    const float inv = 1.0f / (float)P_;
    float4 o; o.x = sx * inv; o.y = sy * inv; o.z = sz * inv; o.w = sw * inv;
    ((float4*)g_node_x)[n * (D_ / 4) + lane] = o;
}

// ===== K2: graph build (128 blocks x 512) ===================================
__global__ void __launch_bounds__(512)
k_graph_build(const int* __restrict__ ei) {
    const int tid = threadIdx.x, bid = blockIdx.x;
    const int idx = bid * 512 + tid;          // 0..65535 == E
    __shared__ int s_scan[512];

    unsigned gen0 = 0;
    if (tid == 0) gen0 = *(volatile unsigned*)&g_barrel;

    // A: degree histogram; zero g_tmp for K3's atomic pool
    atomicAdd(&g_cnt[ei[E_ + idx]], 1);
    if (idx < B_ * H_) g_tmp[idx] = 0.0f;

    gbar128(gen0, 1);

    // B: scan (block 0) + dis/Cseed (blocks 1..8)
    if (bid == 0) {
        int base = tid * 8;
        int vals[8]; int tot = 0;
#pragma unroll
        for (int j = 0; j < 8; j++) { vals[j] = g_cnt[base + j]; tot += vals[j]; }
        s_scan[tid] = tot;
        __syncthreads();
        for (int off = 1; off < 512; off <<= 1) {
            int x = (tid >= off) ? s_scan[tid - off] : 0;
            __syncthreads();
            s_scan[tid] += x;
            __syncthreads();
        }
        int excl = s_scan[tid] - tot;
#pragma unroll
        for (int j = 0; j < 8; j++) { g_offs[base + j] = excl; excl += vals[j]; }
        if (tid == 511) g_offs[N_] = excl;
    } else if (bid <= 8) {
        int i = (bid - 1) * 512 + tid;
        float dv = rsqrtf((float)(g_cnt[i] + 1));
        g_dis[i] = dv;
        g_C[i * B_ + (i >> 7)] = dv * dv;     // self-loop seed (overwrite)
    }

    gbar128(gen0, 2);

    // C: scatter into CSR + C; zero cnt for next replay
    if (idx < N_) g_cnt[idx] = 0;
    {
        int u = ei[idx];
        int v = ei[E_ + idx];
        float w = g_dis[u] * g_dis[v];
        int pos = g_offs[v] + atomicAdd(&g_cursor[v], 1);
        g_csr_src[pos] = u;
        g_csr_w[pos]   = w;
        atomicAdd(&g_C[u * B_ + (v >> 7)], w);
    }
}

// ===== K3: aggregate -> GEMM(relu) -> pool(atomic) (128 blocks x 1024) ======
__global__ void __launch_bounds__(1024)
k_agp(const float* __restrict__ W1, const float* __restrict__ b1) {
    const int tid = threadIdx.x, bid = blockIdx.x;
    const int idx = bid * 1024 + tid;

    __shared__ __align__(16) float As[32 * 256];     // 32768 B
    __shared__ __align__(16) float Bs[8 * 256];      //  8192 B
    __shared__ __align__(16) float sC[32 * 33];      //  4224 B
    float* Xs = As;                                  // alias post-GEMM

    if (idx < N_) g_cursor[idx] = 0;                 // reset for next replay
    sC[(tid >> 5) * 33 + (tid & 31)] = g_C[bid * 1024 + tid];

    // aggregate 32 nodes into As[m][k]
    {
        const int group = tid >> 8;          // 0..3
        const int d = tid & 255;
#pragma unroll 1
        for (int vv = 0; vv < 8; vv++) {
            int ml = group * 8 + vv;
            int v = bid * 32 + ml;
            int beg = g_offs[v], end = g_offs[v + 1];
            float dv = g_dis[v];
            float acc = dv * dv * g_node_x[v * D_ + d];
            float a0 = 0, a1 = 0, a2 = 0, a3 = 0, a4 = 0, a5 = 0, a6 = 0, a7 = 0;
            int i = beg;
            for (; i + 8 <= end; i += 8) {
                int u0 = g_csr_src[i + 0], u1 = g_csr_src[i + 1];
                int u2 = g_csr_src[i + 2], u3 = g_csr_src[i + 3];
                int u4 = g_csr_src[i + 4], u5 = g_csr_src[i + 5];
                int u6 = g_csr_src[i + 6], u7 = g_csr_src[i + 7];
                float w0 = g_csr_w[i + 0], w1 = g_csr_w[i + 1];
                float w2 = g_csr_w[i + 2], w3 = g_csr_w[i + 3];
                float w4 = g_csr_w[i + 4], w5 = g_csr_w[i + 5];
                float w6 = g_csr_w[i + 6], w7 = g_csr_w[i + 7];
                a0 += w0 * g_node_x[u0 * D_ + d];
                a1 += w1 * g_node_x[u1 * D_ + d];
                a2 += w2 * g_node_x[u2 * D_ + d];
                a3 += w3 * g_node_x[u3 * D_ + d];
                a4 += w4 * g_node_x[u4 * D_ + d];
                a5 += w5 * g_node_x[u5 * D_ + d];
                a6 += w6 * g_node_x[u6 * D_ + d];
                a7 += w7 * g_node_x[u7 * D_ + d];
            }
            for (; i < end; i++) a0 += g_csr_w[i] * g_node_x[g_csr_src[i] * D_ + d];
            acc += ((a0 + a1) + (a2 + a3)) + ((a4 + a5) + (a6 + a7));
            As[ml * 256 + d] = acc;
        }
    }
    __syncthreads();

    // GEMM: 256 compute threads (4m x 8n), A register-chunked; 512 loaders
    {
        const int mg = tid >> 5;             // 0..7 (warp-uniform m group)
        const int tn = tid & 31;             // 0..31
        unsigned long long acc[4][4];
#pragma unroll
        for (int mi = 0; mi < 4; mi++)
#pragma unroll
            for (int p = 0; p < 4; p++) acc[mi][p] = 0ull;

        const int lp = tid - 512;
        for (int t = 0; t < 32; t++) {
            if (tid >= 512) {   // load W1 tile 8x256, one float4 each
                int row = lp >> 6, nq = (lp & 63) * 4;
                *(float4*)&Bs[row * 256 + nq] = *(const float4*)&W1[(t * 8 + row) * 256 + nq];
            }
            __syncthreads();
            if (tid < 256) {
#pragma unroll
                for (int half = 0; half < 2; half++) {
                    // A chunk: 4 m rows x 4 k, broadcast LDS.128 -> registers
                    float4 av[4];
#pragma unroll
                    for (int mi = 0; mi < 4; mi++)
                        av[mi] = *(const float4*)&As[(mg * 4 + mi) * 256 + t * 8 + half * 4];
#pragma unroll
                    for (int kk2 = 0; kk2 < 4; kk2++) {
                        int kk = half * 4 + kk2;
                        ulonglong2 bp0 = *(const ulonglong2*)&Bs[kk * 256 + tn * 4];
                        ulonglong2 bp1 = *(const ulonglong2*)&Bs[kk * 256 + 128 + tn * 4];
                        unsigned long long a0 = pk2(kk2 == 0 ? av[0].x : kk2 == 1 ? av[0].y : kk2 == 2 ? av[0].z : av[0].w);
                        unsigned long long a1 = pk2(kk2 == 0 ? av[1].x : kk2 == 1 ? av[1].y : kk2 == 2 ? av[1].z : av[1].w);
                        unsigned long long a2 = pk2(kk2 == 0 ? av[2].x : kk2 == 1 ? av[2].y : kk2 == 2 ? av[2].z : av[2].w);
                        unsigned long long a3 = pk2(kk2 == 0 ? av[3].x : kk2 == 1 ? av[3].y : kk2 == 2 ? av[3].z : av[3].w);
                        acc[0][0] = ffma2(a0, bp0.x, acc[0][0]); acc[0][1] = ffma2(a0, bp0.y, acc[0][1]);
                        acc[0][2] = ffma2(a0, bp1.x, acc[0][2]); acc[0][3] = ffma2(a0, bp1.y, acc[0][3]);
                        acc[1][0] = ffma2(a1, bp0.x, acc[1][0]); acc[1][1] = ffma2(a1, bp0.y, acc[1][1]);
                        acc[1][2] = ffma2(a1, bp1.x, acc[1][2]); acc[1][3] = ffma2(a1, bp1.y, acc[1][3]);
                        acc[2][0] = ffma2(a2, bp0.x, acc[2][0]); acc[2][1] = ffma2(a2, bp0.y, acc[2][1]);
                        acc[2][2] = ffma2(a2, bp1.x, acc[2][2]); acc[2][3] = ffma2(a2, bp1.y, acc[2][3]);
                        acc[3][0] = ffma2(a3, bp0.x, acc[3][0]); acc[3][1] = ffma2(a3, bp0.y, acc[3][1]);
                        acc[3][2] = ffma2(a3, bp1.x, acc[3][2]); acc[3][3] = ffma2(a3, bp1.y, acc[3][3]);
                    }
                }
            }
            __syncthreads();
        }

        if (tid < 256) {
            float bb[2][4];
#pragma unroll
            for (int j = 0; j < 4; j++) { bb[0][j] = b1[tn * 4 + j]; bb[1][j] = b1[128 + tn * 4 + j]; }
            __syncthreads();   // As reads complete everywhere before overwrite
#pragma unroll
            for (int mi = 0; mi < 4; mi++) {
                int m = mg * 4 + mi;
#pragma unroll
                for (int c = 0; c < 2; c++) {
#pragma unroll
                    for (int p = 0; p < 2; p++) {
                        unsigned long long a = acc[mi][c * 2 + p];
                        float lo = __uint_as_float((unsigned)(a & 0xffffffffull));
                        float hi = __uint_as_float((unsigned)(a >> 32));
                        float2 o;
                        o.x = fmaxf(lo + bb[c][p * 2 + 0], 0.0f);
                        o.y = fmaxf(hi + bb[c][p * 2 + 1], 0.0f);
                        *(float2*)&Xs[m * 256 + c * 128 + tn * 4 + p * 2] = o;
                    }
                }
            }
        } else {
            __syncthreads();   // matching barrier for non-compute threads
        }
    }
    __syncthreads();

    // pool (b-split): thread (q,d) accumulates 8 batch values over 32 rows,
    // then 8 atomic adds straight into g_tmp (no partial buffer)
    {
        const int q = tid >> 8, d = tid & 255;
        float pacc[8];
#pragma unroll
        for (int bi = 0; bi < 8; bi++) pacc[bi] = 0.0f;
        for (int ml = 0; ml < 32; ml++) {
            float x = Xs[ml * 256 + d];
#pragma unroll
            for (int bi = 0; bi < 8; bi++) pacc[bi] += sC[ml * 33 + q * 8 + bi] * x;
        }
#pragma unroll
        for (int bi = 0; bi < 8; bi++)
            atomicAdd(&g_tmp[(q * 8 + bi) * 256 + d], pacc[bi]);
    }
}

// ===== K4: out = tmp @ W2 / NG + b2 (32 blocks x 256); zero C ===============
__global__ void __launch_bounds__(256)
k_final2(const float* __restrict__ W2, const float* __restrict__ b2,
         float* __restrict__ out) {
    const int tid = threadIdx.x, b = blockIdx.x;
    __shared__ float sm[256];

    // zero C for next replay (each block 16 floats/thread)
    {
        int base = (b * 256 + tid) * 16;
#pragma unroll
        for (int j = 0; j < 16; j++) g_C[base + j] = 0.0f;
    }

    sm[tid] = g_tmp[b * 256 + tid];
    __syncthreads();
    float acc = 0.0f;
    const float* w2 = W2 + tid;
#pragma unroll 16
    for (int d = 0; d < 256; d++) acc += sm[d] * w2[d * 256];
    out[b * 256 + tid] = acc * (1.0f / NG_) + b2[tid];
}

// ---------------- launch -----------------------------------------------------
extern "C" void kernel_launch(void* const* d_in, const int* in_sizes, int n_in,
                              void* d_out, int out_size) {
    const float* dge  = (const float*)d_in[0];
    const int*   gids = (const int*)  d_in[1];
    const int*   ei   = (const int*)  d_in[2];
    const float* W1   = (const float*)d_in[3];
    const float* b1   = (const float*)d_in[4];
    const float* W2   = (const float*)d_in[5];
    const float* b2   = (const float*)d_in[6];
    float* out = (float*)d_out;

    k_node_mean<<<1024, 256>>>(dge, gids);
    k_graph_build<<<128, 512>>>(ei);
    k_agp<<<128, 1024>>>(W1, b1);
    k_final2<<<32, 256>>>(W2, b2, out);
}

// round 16
// speedup vs baseline: 1.6154x; 1.0795x over previous
#include <cuda_runtime.h>
#include <cuda_bf16.h>

// Shapes (fixed)
#define B_   32
#define P_   16
#define S_   256
#define D_   256
#define NG_  128
#define N_   4096
#define E_   65536
#define H_   256

// ---------------- scratch ----------------------------------------------------
__device__ __align__(16) float g_node_x[N_ * D_];
__device__ float g_dis[N_];
__device__ int   g_cnt[N_];      // zeroed in k_graph_build phase C
__device__ int   g_cursor[N_];   // zeroed in k_agp
__device__ int   g_offs[N_ + 1];
__device__ __align__(16) int   g_csr_src[E_];
__device__ __align__(16) float g_csr_w[E_];
__device__ float g_C[N_ * B_];   // zeroed in k_node_mean each launch
__device__ float g_tmp[B_ * H_]; // pool accumulator; zeroed in k_graph_build

// grid barrier (used only inside k_graph_build, 128 blocks)
__device__ unsigned g_barcnt;
__device__ unsigned g_barrel;

__device__ __forceinline__ void gbar128(unsigned gen0, unsigned k) {
    __syncthreads();
    if (threadIdx.x == 0) {
        __threadfence();
        unsigned a = atomicAdd(&g_barcnt, 1u);
        if (a == 127u) {
            g_barcnt = 0;
            __threadfence();
            atomicAdd(&g_barrel, 1u);
        } else {
            for (long long it = 0; it < 50000000LL; ++it) {
                unsigned cur = *(volatile unsigned*)&g_barrel;
                if (cur - gen0 >= k) break;
                __nanosleep(32);
            }
        }
        __threadfence();
    }
    __syncthreads();
}

// packed fp32x2 helpers
__device__ __forceinline__ unsigned long long ffma2(unsigned long long a,
                                                    unsigned long long b,
                                                    unsigned long long c) {
    unsigned long long d;
    asm("fma.rn.f32x2 %0, %1, %2, %3;" : "=l"(d) : "l"(a), "l"(b), "l"(c));
    return d;
}
__device__ __forceinline__ unsigned long long pk2(float x) {
    unsigned long long r; unsigned u = __float_as_uint(x);
    asm("mov.b64 %0, {%1, %2};" : "=l"(r) : "r"(u), "r"(u));
    return r;
}

// ===== K1: node_mean + zero C (1024 blocks x 256) ===========================
__global__ void __launch_bounds__(256)
k_node_mean(const float* __restrict__ dge, const int* __restrict__ gids) {
    int t = blockIdx.x * 256 + threadIdx.x;   // 0..262143
    if (t < N_ * B_) g_C[t] = 0.0f;           // zero C (seeded/accumulated in K2)
    int n = t >> 6, lane = t & 63;
    int b = n >> 7;
    int g = __ldg(&gids[n]);
    const float4* base = (const float4*)(dge + ((size_t)(b * P_ * S_ + g)) * D_) + lane;
    float4 v[16];
#pragma unroll
    for (int p = 0; p < 16; p++) v[p] = base[p * (S_ * D_ / 4)];
    float sx = 0, sy = 0, sz = 0, sw = 0;
#pragma unroll
    for (int p = 0; p < 16; p++) { sx += v[p].x; sy += v[p].y; sz += v[p].z; sw += v[p].w; }
    const float inv = 1.0f / (float)P_;
    float4 o; o.x = sx * inv; o.y = sy * inv; o.z = sz * inv; o.w = sw * inv;
    ((float4*)g_node_x)[n * (D_ / 4) + lane] = o;
}

// ===== K2: graph build (128 blocks x 512) ===================================
__global__ void __launch_bounds__(512)
k_graph_build(const int* __restrict__ ei) {
    const int tid = threadIdx.x, bid = blockIdx.x;
    const int idx = bid * 512 + tid;          // 0..65535 == E
    __shared__ int s_scan[512];

    unsigned gen0 = 0;
    if (tid == 0) gen0 = *(volatile unsigned*)&g_barrel;

    // A: degree histogram; zero g_tmp for K3's atomic pool
    atomicAdd(&g_cnt[ei[E_ + idx]], 1);
    if (idx < B_ * H_) g_tmp[idx] = 0.0f;

    gbar128(gen0, 1);

    // B: scan (block 0) + dis/Cseed (blocks 1..8)
    if (bid == 0) {
        int base = tid * 8;
        int vals[8]; int tot = 0;
#pragma unroll
        for (int j = 0; j < 8; j++) { vals[j] = g_cnt[base + j]; tot += vals[j]; }
        s_scan[tid] = tot;
        __syncthreads();
        for (int off = 1; off < 512; off <<= 1) {
            int x = (tid >= off) ? s_scan[tid - off] : 0;
            __syncthreads();
            s_scan[tid] += x;
            __syncthreads();
        }
        int excl = s_scan[tid] - tot;
#pragma unroll
        for (int j = 0; j < 8; j++) { g_offs[base + j] = excl; excl += vals[j]; }
        if (tid == 511) g_offs[N_] = excl;
    } else if (bid <= 8) {
        int i = (bid - 1) * 512 + tid;
        float dv = rsqrtf((float)(g_cnt[i] + 1));
        g_dis[i] = dv;
        g_C[i * B_ + (i >> 7)] = dv * dv;     // self-loop seed
    }

    gbar128(gen0, 2);

    // C: scatter into CSR + C; zero cnt for next replay
    if (idx < N_) g_cnt[idx] = 0;
    {
        int u = ei[idx];
        int v = ei[E_ + idx];
        float w = g_dis[u] * g_dis[v];
        int pos = g_offs[v] + atomicAdd(&g_cursor[v], 1);
        g_csr_src[pos] = u;
        g_csr_w[pos]   = w;
        atomicAdd(&g_C[u * B_ + (v >> 7)], w);
    }
}

// ===== K3: aggregate -> GEMM(relu) -> pool(atomic) (128 blocks x 1024) ======
__global__ void __launch_bounds__(1024)
k_agp(const float* __restrict__ W1, const float* __restrict__ b1) {
    const int tid = threadIdx.x, bid = blockIdx.x;
    const int idx = bid * 1024 + tid;

    __shared__ __align__(16) float As[32 * 256];     // 32768 B
    __shared__ __align__(16) float Bs[8 * 256];      //  8192 B
    __shared__ __align__(16) float sC[32 * 33];      //  4224 B
    float* Xs = As;                                  // alias post-GEMM

    if (idx < N_) g_cursor[idx] = 0;                 // reset for next replay
    sC[(tid >> 5) * 33 + (tid & 31)] = g_C[bid * 1024 + tid];

    // aggregate 32 nodes into As[m][k]
    {
        const int group = tid >> 8;          // 0..3
        const int d = tid & 255;
#pragma unroll 1
        for (int vv = 0; vv < 8; vv++) {
            int ml = group * 8 + vv;
            int v = bid * 32 + ml;
            int beg = g_offs[v], end = g_offs[v + 1];
            float dv = g_dis[v];
            float acc = dv * dv * g_node_x[v * D_ + d];
            float a0 = 0, a1 = 0, a2 = 0, a3 = 0, a4 = 0, a5 = 0, a6 = 0, a7 = 0;
            int i = beg;
            for (; i + 8 <= end; i += 8) {
                int u0 = g_csr_src[i + 0], u1 = g_csr_src[i + 1];
                int u2 = g_csr_src[i + 2], u3 = g_csr_src[i + 3];
                int u4 = g_csr_src[i + 4], u5 = g_csr_src[i + 5];
                int u6 = g_csr_src[i + 6], u7 = g_csr_src[i + 7];
                float w0 = g_csr_w[i + 0], w1 = g_csr_w[i + 1];
                float w2 = g_csr_w[i + 2], w3 = g_csr_w[i + 3];
                float w4 = g_csr_w[i + 4], w5 = g_csr_w[i + 5];
                float w6 = g_csr_w[i + 6], w7 = g_csr_w[i + 7];
                a0 += w0 * g_node_x[u0 * D_ + d];
                a1 += w1 * g_node_x[u1 * D_ + d];
                a2 += w2 * g_node_x[u2 * D_ + d];
                a3 += w3 * g_node_x[u3 * D_ + d];
                a4 += w4 * g_node_x[u4 * D_ + d];
                a5 += w5 * g_node_x[u5 * D_ + d];
                a6 += w6 * g_node_x[u6 * D_ + d];
                a7 += w7 * g_node_x[u7 * D_ + d];
            }
            for (; i < end; i++) a0 += g_csr_w[i] * g_node_x[g_csr_src[i] * D_ + d];
            acc += ((a0 + a1) + (a2 + a3)) + ((a4 + a5) + (a6 + a7));
            As[ml * 256 + d] = acc;
        }
    }
    __syncthreads();

    // GEMM: 256 compute threads (4m x 8n), A register-chunked; 512 loaders
    {
        const int mg = tid >> 5;             // 0..7 (warp-uniform m group)
        const int tn = tid & 31;             // 0..31
        unsigned long long acc[4][4];
#pragma unroll
        for (int mi = 0; mi < 4; mi++)
#pragma unroll
            for (int p = 0; p < 4; p++) acc[mi][p] = 0ull;

        const int lp = tid - 512;
        for (int t = 0; t < 32; t++) {
            if (tid >= 512) {   // load W1 tile 8x256, one float4 each
                int row = lp >> 6, nq = (lp & 63) * 4;
                *(float4*)&Bs[row * 256 + nq] = *(const float4*)&W1[(t * 8 + row) * 256 + nq];
            }
            __syncthreads();
            if (tid < 256) {
#pragma unroll
                for (int half = 0; half < 2; half++) {
                    float4 av[4];
#pragma unroll
                    for (int mi = 0; mi < 4; mi++)
                        av[mi] = *(const float4*)&As[(mg * 4 + mi) * 256 + t * 8 + half * 4];
#pragma unroll
                    for (int kk2 = 0; kk2 < 4; kk2++) {
                        int kk = half * 4 + kk2;
                        ulonglong2 bp0 = *(const ulonglong2*)&Bs[kk * 256 + tn * 4];
                        ulonglong2 bp1 = *(const ulonglong2*)&Bs[kk * 256 + 128 + tn * 4];
                        unsigned long long a0 = pk2(kk2 == 0 ? av[0].x : kk2 == 1 ? av[0].y : kk2 == 2 ? av[0].z : av[0].w);
                        unsigned long long a1 = pk2(kk2 == 0 ? av[1].x : kk2 == 1 ? av[1].y : kk2 == 2 ? av[1].z : av[1].w);
                        unsigned long long a2 = pk2(kk2 == 0 ? av[2].x : kk2 == 1 ? av[2].y : kk2 == 2 ? av[2].z : av[2].w);
                        unsigned long long a3 = pk2(kk2 == 0 ? av[3].x : kk2 == 1 ? av[3].y : kk2 == 2 ? av[3].z : av[3].w);
                        acc[0][0] = ffma2(a0, bp0.x, acc[0][0]); acc[0][1] = ffma2(a0, bp0.y, acc[0][1]);
                        acc[0][2] = ffma2(a0, bp1.x, acc[0][2]); acc[0][3] = ffma2(a0, bp1.y, acc[0][3]);
                        acc[1][0] = ffma2(a1, bp0.x, acc[1][0]); acc[1][1] = ffma2(a1, bp0.y, acc[1][1]);
                        acc[1][2] = ffma2(a1, bp1.x, acc[1][2]); acc[1][3] = ffma2(a1, bp1.y, acc[1][3]);
                        acc[2][0] = ffma2(a2, bp0.x, acc[2][0]); acc[2][1] = ffma2(a2, bp0.y, acc[2][1]);
                        acc[2][2] = ffma2(a2, bp1.x, acc[2][2]); acc[2][3] = ffma2(a2, bp1.y, acc[2][3]);
                        acc[3][0] = ffma2(a3, bp0.x, acc[3][0]); acc[3][1] = ffma2(a3, bp0.y, acc[3][1]);
                        acc[3][2] = ffma2(a3, bp1.x, acc[3][2]); acc[3][3] = ffma2(a3, bp1.y, acc[3][3]);
                    }
                }
            }
            __syncthreads();
        }

        if (tid < 256) {
            float bb[2][4];
#pragma unroll
            for (int j = 0; j < 4; j++) { bb[0][j] = b1[tn * 4 + j]; bb[1][j] = b1[128 + tn * 4 + j]; }
            __syncthreads();   // As reads complete everywhere before overwrite
#pragma unroll
            for (int mi = 0; mi < 4; mi++) {
                int m = mg * 4 + mi;
#pragma unroll
                for (int c = 0; c < 2; c++) {
#pragma unroll
                    for (int p = 0; p < 2; p++) {
                        unsigned long long a = acc[mi][c * 2 + p];
                        float lo = __uint_as_float((unsigned)(a & 0xffffffffull));
                        float hi = __uint_as_float((unsigned)(a >> 32));
                        float2 o;
                        o.x = fmaxf(lo + bb[c][p * 2 + 0], 0.0f);
                        o.y = fmaxf(hi + bb[c][p * 2 + 1], 0.0f);
                        *(float2*)&Xs[m * 256 + c * 128 + tn * 4 + p * 2] = o;
                    }
                }
            }
        } else {
            __syncthreads();   // matching barrier for non-compute threads
        }
    }
    __syncthreads();

    // pool (b-split): thread (q,d) accumulates 8 batch values over 32 rows,
    // then 8 atomic adds straight into g_tmp
    {
        const int q = tid >> 8, d = tid & 255;
        float pacc[8];
#pragma unroll
        for (int bi = 0; bi < 8; bi++) pacc[bi] = 0.0f;
        for (int ml = 0; ml < 32; ml++) {
            float x = Xs[ml * 256 + d];
#pragma unroll
            for (int bi = 0; bi < 8; bi++) pacc[bi] += sC[ml * 33 + q * 8 + bi] * x;
        }
#pragma unroll
        for (int bi = 0; bi < 8; bi++)
            atomicAdd(&g_tmp[(q * 8 + bi) * 256 + d], pacc[bi]);
    }
}

// ===== K4: out = tmp @ W2 / NG + b2 (256 blocks x 256) ======================
// block (b, chunk): 32 h-columns; 8 warps each own a 32-d slice; smem reduce.
__global__ void __launch_bounds__(256)
k_final3(const float* __restrict__ W2, const float* __restrict__ b2,
         float* __restrict__ out) {
    const int tid = threadIdx.x;
    const int b = blockIdx.x >> 3, chunk = blockIdx.x & 7;
    const int lane = tid & 31, warp = tid >> 5;
    const int h = chunk * 32 + lane;
    __shared__ float red[8][32];

    const float* tr = g_tmp + b * 256 + warp * 32;
    const float* w2 = W2 + (warp * 32) * 256 + h;
    float acc = 0.0f;
#pragma unroll
    for (int d = 0; d < 32; d++) acc += tr[d] * w2[d * 256];
    red[warp][lane] = acc;
    __syncthreads();
    if (warp == 0) {
        float s = red[0][lane];
#pragma unroll
        for (int w = 1; w < 8; w++) s += red[w][lane];
        out[b * 256 + h] = s * (1.0f / NG_) + b2[h];
    }
}

// ---------------- launch -----------------------------------------------------
extern "C" void kernel_launch(void* const* d_in, const int* in_sizes, int n_in,
                              void* d_out, int out_size) {
    const float* dge  = (const float*)d_in[0];
    const int*   gids = (const int*)  d_in[1];
    const int*   ei   = (const int*)  d_in[2];
    const float* W1   = (const float*)d_in[3];
    const float* b1   = (const float*)d_in[4];
    const float* W2   = (const float*)d_in[5];
    const float* b2   = (const float*)d_in[6];
    float* out = (float*)d_out;

    k_node_mean<<<1024, 256>>>(dge, gids);
    k_graph_build<<<128, 512>>>(ei);
    k_agp<<<128, 1024>>>(W1, b1);
    k_final3<<<256, 256>>>(W2, b2, out);
}